// round 1
// baseline (speedup 1.0000x reference)
#include <cuda_runtime.h>
#include <cuda_bf16.h>
#include <cstdint>

// Problem constants
#define NPTS   64
#define NANGS  2016           // 64*63/2
#define NCOLS  300000
#define NPAIRS (NCOLS / 2)    // 150000 column-pairs (f32x2 packed)

// Scratch for R (64x64, row-major [row][col]) built by kernel 1, read by kernel 2.
__device__ float g_R[NPTS * NPTS];

// ---------------------------------------------------------------------------
// Kernel 1: build R = diag(mus) * G_{2015} ... G_0  (single block, 64 threads)
// Thread j owns column j of R. Rotations mix rows (t,b) independently per
// column, so no cross-thread communication is needed after the cos/sin fill.
// Within a fixed t-group, row-t's value lives in a register -> critical path
// is ~1 FFMA per rotation.
// ---------------------------------------------------------------------------
__global__ void __launch_bounds__(NPTS, 1)
build_R_kernel(const float* __restrict__ angles, const float* __restrict__ mus) {
    __shared__ float Rs[NPTS * NPTS];
    __shared__ float cs_c[NANGS];
    __shared__ float cs_s[NANGS];

    const int j = threadIdx.x;  // column index, 0..63

    // Cooperative cos/sin precompute
    for (int i = j; i < NANGS; i += NPTS) {
        float sv, cv;
        sincosf(angles[i], &sv, &cv);
        cs_c[i] = cv;
        cs_s[i] = sv;
    }
    // Init column j of identity
    for (int r = 0; r < NPTS; r++) Rs[r * NPTS + j] = (r == j) ? 1.0f : 0.0f;
    __syncthreads();

    // Sequential Givens chain in lexicographic (t,b) order = np.triu_indices(64, 1)
    int i = 0;
    for (int t = 0; t < NPTS - 1; t++) {
        float rt = Rs[t * NPTS + j];
        for (int b = t + 1; b < NPTS; b++, i++) {
            const float c = cs_c[i];
            const float s = cs_s[i];
            const float rb = Rs[b * NPTS + j];
            const float nrb = fmaf(s, rt, c * rb);     // s*rt_old + c*rb_old
            rt = fmaf(c, rt, -(s * rb));               // c*rt_old - s*rb_old
            Rs[b * NPTS + j] = nrb;
        }
        Rs[t * NPTS + j] = rt;
    }

    // Apply mus (row scaling) and publish. No sync needed: column-private.
    for (int r = 0; r < NPTS; r++) g_R[r * NPTS + j] = mus[r] * Rs[r * NPTS + j];
}

// ---------------------------------------------------------------------------
// Kernel 2: Y = R @ X, FP32 via packed fma.rn.f32x2.
// Each thread owns one pair of adjacent columns (one 64-bit lane), keeps all
// 64 output rows as packed f32x2 accumulators (128 regs), and streams k=0..63:
//   load X[k][c:c+2] (LDG.64, coalesced), then 64x FFMA2 with R[r][k]
//   duplicated into both halves (LDS.64 broadcast from smem -> conflict-free).
// ---------------------------------------------------------------------------
__global__ void __launch_bounds__(128, 1)
gemm_f32x2_kernel(const float* __restrict__ X, float* __restrict__ Y) {
    __shared__ unsigned long long Rdup[NPTS * NPTS];  // 32 KB: (R[r][k], R[r][k])

    // Stage duplicated R into smem
    for (int i = threadIdx.x; i < NPTS * NPTS; i += 128) {
        const unsigned int b = __float_as_uint(g_R[i]);
        Rdup[i] = ((unsigned long long)b << 32) | (unsigned long long)b;
    }
    __syncthreads();

    const int p = blockIdx.x * 128 + threadIdx.x;  // column-pair index
    if (p >= NPAIRS) return;

    unsigned long long acc[NPTS];
#pragma unroll
    for (int r = 0; r < NPTS; r++) acc[r] = 0ull;

    const unsigned long long* __restrict__ Xp =
        reinterpret_cast<const unsigned long long*>(X);

    for (int k = 0; k < NPTS; k++) {
        const unsigned long long xk = Xp[(size_t)k * NPAIRS + p];
#pragma unroll
        for (int r = 0; r < NPTS; r++) {
            const unsigned long long rv = Rdup[r * NPTS + k];
            asm("fma.rn.f32x2 %0, %1, %2, %3;"
                : "=l"(acc[r])
                : "l"(rv), "l"(xk), "l"(acc[r]));
        }
    }

    unsigned long long* __restrict__ Yp = reinterpret_cast<unsigned long long*>(Y);
#pragma unroll
    for (int r = 0; r < NPTS; r++) {
        Yp[(size_t)r * NPAIRS + p] = acc[r];
    }
}

// ---------------------------------------------------------------------------
// Launch: inputs in metadata order: X (64*300000 f32), angles (2016 f32),
// mus (64 f32). Output: 64*300000 f32.
// ---------------------------------------------------------------------------
extern "C" void kernel_launch(void* const* d_in, const int* in_sizes, int n_in,
                              void* d_out, int out_size) {
    const float* X      = (const float*)d_in[0];
    const float* angles = (const float*)d_in[1];
    const float* mus    = (const float*)d_in[2];
    float* Y            = (float*)d_out;

    build_R_kernel<<<1, NPTS>>>(angles, mus);

    const int blocks = (NPAIRS + 127) / 128;  // 1172
    gemm_f32x2_kernel<<<blocks, 128>>>(X, Y);
}

// round 2
// speedup vs baseline: 1.2372x; 1.2372x over previous
#include <cuda_runtime.h>
#include <cuda_bf16.h>
#include <cstdint>

#define NPTS   64
#define NANGS  2016            // 64*63/2
#define NCOLS  300000
#define NPAIRS (NCOLS / 2)     // 150000 f32x2 column-pairs

typedef unsigned long long u64;

// R (64x64 row-major) produced by kernel 1, consumed by kernel 2.
__device__ float g_R[NPTS * NPTS];

// ---------------------------------------------------------------------------
// Kernel 1: build R. Thread j keeps COLUMN j of R entirely in registers;
// the 2016-rotation chain is fully unrolled (critical path ~1 FFMA / rotation).
// ---------------------------------------------------------------------------
__global__ void __launch_bounds__(NPTS, 1)
build_R_kernel(const float* __restrict__ angles, const float* __restrict__ mus) {
    __shared__ float cs_c[NANGS];
    __shared__ float cs_s[NANGS];

    const int j = threadIdx.x;

    for (int i = j; i < NANGS; i += NPTS) {
        float sv, cv;
        __sincosf(angles[i], &sv, &cv);
        cs_c[i] = cv;
        cs_s[i] = sv;
    }
    __syncthreads();

    float Rc[NPTS];
#pragma unroll
    for (int r = 0; r < NPTS; r++) Rc[r] = (r == j) ? 1.0f : 0.0f;

    int i = 0;
#pragma unroll
    for (int t = 0; t < NPTS - 1; t++) {
        float rt = Rc[t];
#pragma unroll
        for (int b = t + 1; b < NPTS; b++, i++) {
            const float c = cs_c[i];
            const float s = cs_s[i];
            const float rb = Rc[b];
            Rc[b] = fmaf(s, rt, c * rb);
            rt    = fmaf(c, rt, -(s * rb));
        }
        Rc[t] = rt;
    }

#pragma unroll
    for (int r = 0; r < NPTS; r++) g_R[r * NPTS + j] = mus[r] * Rc[r];
}

// ---------------------------------------------------------------------------
// Kernel 2: Y = R @ X via packed fma.rn.f32x2.
// Block = 256 threads = 8 warps; warp w owns rows [8w, 8w+8).
// Each lane owns 4 column-pairs (p, p+32, p+64, p+96) -> block covers 128 pairs.
// Per k: 4 LDG.64 (double-buffered) + 8 LDS.64 (R broadcast) + 32 FFMA2.
// LDS:FFMA2 = 1:4 so the fma pipe is the binder (~65K cyc/SM).
// ---------------------------------------------------------------------------
#define RG 8   // rows per warp
#define PJ 4   // pairs per thread

__global__ void __launch_bounds__(256, 2)
gemm_f32x2_kernel(const float* __restrict__ X, float* __restrict__ Y) {
    __shared__ u64 Rdup[NPTS * NPTS];   // 32 KB, (R,R) duplicated

    for (int i = threadIdx.x; i < NPTS * NPTS; i += 256) {
        const unsigned int b = __float_as_uint(g_R[i]);
        Rdup[i] = ((u64)b << 32) | (u64)b;
    }
    __syncthreads();

    const int warp = threadIdx.x >> 5;
    const int lane = threadIdx.x & 31;
    const int r0   = warp * RG;

    int  p[PJ];
    bool valid[PJ];
#pragma unroll
    for (int jj = 0; jj < PJ; jj++) {
        p[jj]     = blockIdx.x * 128 + lane + 32 * jj;
        valid[jj] = (p[jj] < NPAIRS);
        if (!valid[jj]) p[jj] = NPAIRS - 1;   // clamp: loads stay in-bounds
    }

    const u64* __restrict__ Xp = reinterpret_cast<const u64*>(X);
    const u64* xptr[PJ];
#pragma unroll
    for (int jj = 0; jj < PJ; jj++) xptr[jj] = Xp + p[jj];

    u64 acc[RG][PJ];
#pragma unroll
    for (int r = 0; r < RG; r++)
#pragma unroll
        for (int jj = 0; jj < PJ; jj++) acc[r][jj] = 0ull;

    u64 xa[PJ], xb[PJ];
#pragma unroll
    for (int jj = 0; jj < PJ; jj++) { xa[jj] = *xptr[jj]; xptr[jj] += NPAIRS; }

#define COMPUTE(KK, XV)                                                        \
    do {                                                                       \
        _Pragma("unroll")                                                      \
        for (int r = 0; r < RG; r++) {                                         \
            const u64 rv = Rdup[(r0 + r) * NPTS + (KK)];                       \
            _Pragma("unroll")                                                  \
            for (int jj = 0; jj < PJ; jj++) {                                  \
                asm("fma.rn.f32x2 %0, %1, %2, %3;"                             \
                    : "=l"(acc[r][jj])                                         \
                    : "l"(rv), "l"(XV[jj]), "l"(acc[r][jj]));                  \
            }                                                                  \
        }                                                                      \
    } while (0)

    for (int k = 0; k < NPTS; k += 2) {
        // prefetch k+1
#pragma unroll
        for (int jj = 0; jj < PJ; jj++) { xb[jj] = *xptr[jj]; xptr[jj] += NPAIRS; }
        COMPUTE(k, xa);
        // prefetch k+2 (last iteration reloads k=1's slot harmlessly in-bounds? no:
        // guard — on k==62 we'd read k==64 OOB. Prefetch only when k+2 < NPTS.)
        if (k + 2 < NPTS) {
#pragma unroll
            for (int jj = 0; jj < PJ; jj++) { xa[jj] = *xptr[jj]; xptr[jj] += NPAIRS; }
        }
        COMPUTE(k + 1, xb);
    }
#undef COMPUTE

    u64* __restrict__ Yp = reinterpret_cast<u64*>(Y);
#pragma unroll
    for (int r = 0; r < RG; r++) {
        u64* yrow = Yp + (size_t)(r0 + r) * NPAIRS;
#pragma unroll
        for (int jj = 0; jj < PJ; jj++) {
            if (valid[jj]) yrow[p[jj]] = acc[r][jj];
        }
    }
}

// ---------------------------------------------------------------------------
// Inputs (metadata order): X (64*300000 f32), angles (2016 f32), mus (64 f32).
// ---------------------------------------------------------------------------
extern "C" void kernel_launch(void* const* d_in, const int* in_sizes, int n_in,
                              void* d_out, int out_size) {
    const float* X      = (const float*)d_in[0];
    const float* angles = (const float*)d_in[1];
    const float* mus    = (const float*)d_in[2];
    float* Y            = (float*)d_out;

    build_R_kernel<<<1, NPTS>>>(angles, mus);

    const int blocks = (NPAIRS + 127) / 128;   // 1172
    gemm_f32x2_kernel<<<blocks, 256>>>(X, Y);
}

// round 3
// speedup vs baseline: 2.0227x; 1.6350x over previous
#include <cuda_runtime.h>
#include <cuda_bf16.h>
#include <cstdint>

#define NPTS   64
#define NANGS  2016
#define NCOLS  300000

typedef unsigned int u32;

// R (64x64 row-major, fp32) produced by kernel 1.
__device__ float g_R[NPTS * NPTS];

// ---------------------------------------------------------------------------
// Kernel 1: build R. Thread j owns column j (state in smem). Loops kept
// ROLLED (small code body) to avoid the single-block I$-throttle regime.
// Critical path: one FFMA per rotation on the carried rt register.
// ---------------------------------------------------------------------------
__global__ void __launch_bounds__(NPTS, 1)
build_R_kernel(const float* __restrict__ angles, const float* __restrict__ mus) {
    __shared__ float cs_c[NANGS];
    __shared__ float cs_s[NANGS];
    __shared__ float Rs[NPTS * NPTS];

    const int j = threadIdx.x;

    for (int i = j; i < NANGS; i += NPTS) {
        float sv, cv;
        __sincosf(angles[i], &sv, &cv);
        cs_c[i] = cv;
        cs_s[i] = sv;
    }
    for (int r = 0; r < NPTS; r++) Rs[r * NPTS + j] = (r == j) ? 1.0f : 0.0f;
    __syncthreads();

    int i = 0;
#pragma unroll 1
    for (int t = 0; t < NPTS - 1; t++) {
        float rt = Rs[t * NPTS + j];
#pragma unroll 1
        for (int b = t + 1; b < NPTS; b++, i++) {
            const float c  = cs_c[i];
            const float s  = cs_s[i];
            const float rb = Rs[b * NPTS + j];
            Rs[b * NPTS + j] = fmaf(s, rt, c * rb);
            rt = fmaf(c, rt, -(s * rb));
        }
        Rs[t * NPTS + j] = rt;
    }

    for (int r = 0; r < NPTS; r++) g_R[r * NPTS + j] = mus[r] * Rs[r * NPTS + j];
}

// ---------------------------------------------------------------------------
// Kernel 2: Y = R @ X via bf16 split-precision HMMA (3-term):
//   Y ~= Rhi@Xhi + Rhi@Xlo + Rlo@Xhi   (fp32 accumulate; Rlo@Xlo ~ 4e-6, dropped)
//
// Block = 256 threads (8 warps), warp tile = 64 rows x 16 cols.
// R packed as bf16x2 (k-pairs) in smem, stride 36 words -> conflict-free
// for the mma A-fragment access pattern (bank = (4g + t) % 32, all distinct).
// X loaded as fp32, split in registers, double-buffered across k-steps.
// ---------------------------------------------------------------------------
#define LDR 36

#define CVT_PACK(d, x1, x0) \
    asm("cvt.rn.bf16x2.f32 %0, %1, %2;" : "=r"(d) : "f"(x1), "f"(x0))

#define MMA_BF16(ACC, A0, A1, A2, A3, B0, B1)                                  \
    asm volatile(                                                              \
        "mma.sync.aligned.m16n8k16.row.col.f32.bf16.bf16.f32 "                 \
        "{%0,%1,%2,%3},{%4,%5,%6,%7},{%8,%9},{%0,%1,%2,%3};"                   \
        : "+f"(ACC[0]), "+f"(ACC[1]), "+f"(ACC[2]), "+f"(ACC[3])               \
        : "r"(A0), "r"(A1), "r"(A2), "r"(A3), "r"(B0), "r"(B1))

__global__ void __launch_bounds__(256, 2)
gemm_hmma_kernel(const float* __restrict__ X, float* __restrict__ Y) {
    __shared__ u32 RhiS[NPTS * LDR];
    __shared__ u32 RloS[NPTS * LDR];

    // Pack R -> (hi, lo) bf16x2 along k-pairs
    for (int idx = threadIdx.x; idx < NPTS * 32; idx += 256) {
        const int row = idx >> 5, kp = idx & 31;
        const float x0 = g_R[row * NPTS + 2 * kp];
        const float x1 = g_R[row * NPTS + 2 * kp + 1];
        u32 h; CVT_PACK(h, x1, x0);
        const float h0 = __uint_as_float(h << 16);
        const float h1 = __uint_as_float(h & 0xFFFF0000u);
        const float l0 = x0 - h0;
        const float l1 = x1 - h1;
        u32 l; CVT_PACK(l, l1, l0);
        RhiS[row * LDR + kp] = h;
        RloS[row * LDR + kp] = l;
    }
    __syncthreads();

    const int warp = threadIdx.x >> 5;
    const int lane = threadIdx.x & 31;
    const int g = lane >> 2;   // group-of-4 id
    const int t = lane & 3;    // id within group

    const long n0 = (long)blockIdx.x * 128 + warp * 16;
    if (n0 + 16 > NCOLS) return;   // tiles divide 300000 exactly; skip overhang warps

    float acc[4][2][4];
#pragma unroll
    for (int mt = 0; mt < 4; mt++)
#pragma unroll
        for (int nt = 0; nt < 2; nt++)
#pragma unroll
            for (int q = 0; q < 4; q++) acc[mt][nt][q] = 0.0f;

    const float* __restrict__ xc0 = X + n0 + g;        // nt = 0 column
    const float* __restrict__ xc1 = X + n0 + 8 + g;    // nt = 1 column

    float raw[2][8];

#define LOADK(BUF, KS)                                                         \
    do {                                                                       \
        const size_t o  = (size_t)((KS)*16 + 2 * t) * NCOLS;                   \
        const size_t o8 = o + (size_t)8 * NCOLS;                               \
        raw[BUF][0] = xc0[o];           raw[BUF][1] = xc0[o + NCOLS];          \
        raw[BUF][2] = xc0[o8];          raw[BUF][3] = xc0[o8 + NCOLS];         \
        raw[BUF][4] = xc1[o];           raw[BUF][5] = xc1[o + NCOLS];          \
        raw[BUF][6] = xc1[o8];          raw[BUF][7] = xc1[o8 + NCOLS];         \
    } while (0)

    LOADK(0, 0);

#pragma unroll
    for (int ks = 0; ks < 4; ks++) {
        const int cur = ks & 1;
        if (ks < 3) LOADK(cur ^ 1, ks + 1);

        // Split X into bf16 hi/lo fragments (B frags for 2 n-tiles)
        u32 bhi[2][2], blo[2][2];
#pragma unroll
        for (int nt = 0; nt < 2; nt++) {
#pragma unroll
            for (int h2 = 0; h2 < 2; h2++) {   // b0 (k..k+1), b1 (k+8..k+9)
                const float x0 = raw[cur][nt * 4 + h2 * 2];
                const float x1 = raw[cur][nt * 4 + h2 * 2 + 1];
                u32 h; CVT_PACK(h, x1, x0);
                const float h0 = __uint_as_float(h << 16);
                const float h1 = __uint_as_float(h & 0xFFFF0000u);
                u32 l; CVT_PACK(l, x1 - h1, x0 - h0);
                bhi[nt][h2] = h;
                blo[nt][h2] = l;
            }
        }

#pragma unroll
        for (int mt = 0; mt < 4; mt++) {
            const int ab = (mt * 16 + g) * LDR + ks * 8;
            const u32 ah0 = RhiS[ab + t];
            const u32 ah1 = RhiS[ab + 8 * LDR + t];
            const u32 ah2 = RhiS[ab + t + 4];
            const u32 ah3 = RhiS[ab + 8 * LDR + t + 4];
            const u32 al0 = RloS[ab + t];
            const u32 al1 = RloS[ab + 8 * LDR + t];
            const u32 al2 = RloS[ab + t + 4];
            const u32 al3 = RloS[ab + 8 * LDR + t + 4];
#pragma unroll
            for (int nt = 0; nt < 2; nt++) {
                MMA_BF16(acc[mt][nt], ah0, ah1, ah2, ah3, bhi[nt][0], bhi[nt][1]);
                MMA_BF16(acc[mt][nt], ah0, ah1, ah2, ah3, blo[nt][0], blo[nt][1]);
                MMA_BF16(acc[mt][nt], al0, al1, al2, al3, bhi[nt][0], bhi[nt][1]);
            }
        }
    }
#undef LOADK

    // Epilogue: each lane stores 2 float2 per (mt, nt)
#pragma unroll
    for (int mt = 0; mt < 4; mt++) {
        const int r0 = mt * 16 + g;
#pragma unroll
        for (int nt = 0; nt < 2; nt++) {
            const long col = n0 + 8 * nt + 2 * t;
            float2 v0 = make_float2(acc[mt][nt][0], acc[mt][nt][1]);
            float2 v1 = make_float2(acc[mt][nt][2], acc[mt][nt][3]);
            *reinterpret_cast<float2*>(Y + (size_t)r0 * NCOLS + col)       = v0;
            *reinterpret_cast<float2*>(Y + (size_t)(r0 + 8) * NCOLS + col) = v1;
        }
    }
}

// ---------------------------------------------------------------------------
// Inputs (metadata order): X (64*300000 f32), angles (2016 f32), mus (64 f32).
// ---------------------------------------------------------------------------
extern "C" void kernel_launch(void* const* d_in, const int* in_sizes, int n_in,
                              void* d_out, int out_size) {
    const float* X      = (const float*)d_in[0];
    const float* angles = (const float*)d_in[1];
    const float* mus    = (const float*)d_in[2];
    float* Y            = (float*)d_out;

    build_R_kernel<<<1, NPTS>>>(angles, mus);

    const int blocks = (NCOLS + 127) / 128;   // 2344, last block partially idle
    gemm_hmma_kernel<<<blocks, 256>>>(X, Y);
}

// round 4
// speedup vs baseline: 2.3154x; 1.1447x over previous
#include <cuda_runtime.h>
#include <cuda_bf16.h>
#include <cstdint>

#define NPTS   64
#define NANGS  2016
#define NCOLS  300000

typedef unsigned int u32;

// R (64x64 row-major, fp32) produced by kernel 1.
__device__ float g_R[NPTS * NPTS];

__device__ __forceinline__ u32 smem_u32(const void* p) {
    u32 a;
    asm("{ .reg .u64 t; cvta.to.shared.u64 t, %1; cvt.u32.u64 %0, t; }"
        : "=r"(a) : "l"(p));
    return a;
}

// ---------------------------------------------------------------------------
// Kernel 1: build R. Thread j owns column j (state in smem, conflict-free).
// (c,s) interleaved as float2 -> one LDS.64 broadcast per rotation.
// ~6 instructions / rotation; rt carried in a register.
// ---------------------------------------------------------------------------
__global__ void __launch_bounds__(NPTS, 1)
build_R_kernel(const float* __restrict__ angles, const float* __restrict__ mus) {
    __shared__ float2 cs[NANGS];
    __shared__ float  Rs[NPTS * NPTS];

    const int j = threadIdx.x;

    for (int i = j; i < NANGS; i += NPTS) {
        float sv, cv;
        __sincosf(angles[i], &sv, &cv);
        cs[i] = make_float2(cv, sv);
    }
    for (int r = 0; r < NPTS; r++) Rs[r * NPTS + j] = (r == j) ? 1.0f : 0.0f;
    __syncthreads();

    int i = 0;
#pragma unroll 1
    for (int t = 0; t < NPTS - 1; t++) {
        float rt = Rs[t * NPTS + j];
#pragma unroll 7
        for (int b = t + 1; b < NPTS; b++, i++) {
            const float2 p  = cs[i];
            const float  rb = Rs[b * NPTS + j];
            Rs[b * NPTS + j] = fmaf(p.y, rt, p.x * rb);
            rt = fmaf(p.x, rt, -(p.y * rb));
        }
        Rs[t * NPTS + j] = rt;
    }

    for (int r = 0; r < NPTS; r++) g_R[r * NPTS + j] = mus[r] * Rs[r * NPTS + j];
}

// ---------------------------------------------------------------------------
// Kernel 2: Y = R @ X via bf16 split-precision HMMA (3-term):
//   Y ~= Rhi@Xhi + Rhi@Xlo + Rlo@Xhi   (fp32 accumulate)
// Warp tile 64x16. A-frags via ldmatrix.x4 (stride-36-word layout is
// conflict-free: 144B row stride -> 16B chunks hit distinct bank quads).
// All 32 X loads issued up-front (MLP), converted per k-step.
// ---------------------------------------------------------------------------
#define LDR 36   // u32 words per R row (32 data + 4 pad); 144 bytes

#define CVT_PACK(d, x1, x0) \
    asm("cvt.rn.bf16x2.f32 %0, %1, %2;" : "=r"(d) : "f"(x1), "f"(x0))

#define LDMX4(R0, R1, R2, R3, ADDR)                                            \
    asm volatile("ldmatrix.sync.aligned.m8n8.x4.shared.b16 {%0,%1,%2,%3}, [%4];" \
                 : "=r"(R0), "=r"(R1), "=r"(R2), "=r"(R3) : "r"(ADDR))

#define MMA_BF16(ACC, A0, A1, A2, A3, B0, B1)                                  \
    asm volatile(                                                              \
        "mma.sync.aligned.m16n8k16.row.col.f32.bf16.bf16.f32 "                 \
        "{%0,%1,%2,%3},{%4,%5,%6,%7},{%8,%9},{%0,%1,%2,%3};"                   \
        : "+f"(ACC[0]), "+f"(ACC[1]), "+f"(ACC[2]), "+f"(ACC[3])               \
        : "r"(A0), "r"(A1), "r"(A2), "r"(A3), "r"(B0), "r"(B1))

__global__ void __launch_bounds__(256, 2)
gemm_hmma_kernel(const float* __restrict__ X, float* __restrict__ Y) {
    __shared__ u32 RhiS[NPTS * LDR];
    __shared__ u32 RloS[NPTS * LDR];

    // Pack R -> (hi, lo) bf16x2 along k-pairs
    for (int idx = threadIdx.x; idx < NPTS * 32; idx += 256) {
        const int row = idx >> 5, kp = idx & 31;
        const float x0 = g_R[row * NPTS + 2 * kp];
        const float x1 = g_R[row * NPTS + 2 * kp + 1];
        u32 h; CVT_PACK(h, x1, x0);
        const float h0 = __uint_as_float(h << 16);
        const float h1 = __uint_as_float(h & 0xFFFF0000u);
        u32 l; CVT_PACK(l, x1 - h1, x0 - h0);
        RhiS[row * LDR + kp] = h;
        RloS[row * LDR + kp] = l;
    }
    __syncthreads();

    const int warp = threadIdx.x >> 5;
    const int lane = threadIdx.x & 31;
    const int g = lane >> 2;
    const int t = lane & 3;

    const long n0 = (long)blockIdx.x * 128 + warp * 16;
    if (n0 + 16 > NCOLS) return;   // overhang warps in last block (after sync)

    // ldmatrix per-lane base address (matrix0: m0-7/k0-7, m8-15/k0-7, m0-7/k8-15, m8-15/k8-15)
    const int r8   = lane & 7;
    const int selm = (lane >> 3) & 1;
    const int selk = (lane >> 4) & 1;
    const u32 laneoff = (u32)(((selm * 8 + r8) * LDR + selk * 4) * 4);
    const u32 ahibase = smem_u32(RhiS) + laneoff;
    const u32 alobase = smem_u32(RloS) + laneoff;

    float acc[4][2][4];
#pragma unroll
    for (int mt = 0; mt < 4; mt++)
#pragma unroll
        for (int nt = 0; nt < 2; nt++)
#pragma unroll
            for (int q = 0; q < 4; q++) acc[mt][nt][q] = 0.0f;

    // ---- all 32 X loads up-front (MLP) ----
    const float* __restrict__ xb = X + n0 + g;
    float raw[4][8];
#pragma unroll
    for (int ks = 0; ks < 4; ks++) {
        const size_t o  = (size_t)(ks * 16 + 2 * t) * NCOLS;
        const size_t o8 = o + (size_t)8 * NCOLS;
        raw[ks][0] = xb[o];      raw[ks][1] = xb[o + NCOLS];
        raw[ks][2] = xb[o8];     raw[ks][3] = xb[o8 + NCOLS];
        raw[ks][4] = xb[o + 8];  raw[ks][5] = xb[o + NCOLS + 8];
        raw[ks][6] = xb[o8 + 8]; raw[ks][7] = xb[o8 + NCOLS + 8];
    }

#pragma unroll
    for (int ks = 0; ks < 4; ks++) {
        // Split X into bf16 hi/lo B-fragments for 2 n-tiles
        u32 bhi[2][2], blo[2][2];
#pragma unroll
        for (int nt = 0; nt < 2; nt++) {
#pragma unroll
            for (int h2 = 0; h2 < 2; h2++) {
                const float x0 = raw[ks][nt * 4 + h2 * 2];
                const float x1 = raw[ks][nt * 4 + h2 * 2 + 1];
                u32 h; CVT_PACK(h, x1, x0);
                const float h0 = __uint_as_float(h << 16);
                const float h1 = __uint_as_float(h & 0xFFFF0000u);
                u32 l; CVT_PACK(l, x1 - h1, x0 - h0);
                bhi[nt][h2] = h;
                blo[nt][h2] = l;
            }
        }

#pragma unroll
        for (int mt = 0; mt < 4; mt++) {
            const u32 off = (u32)(mt * 16 * LDR * 4 + ks * 32);
            u32 ah0, ah1, ah2, ah3, al0, al1, al2, al3;
            LDMX4(ah0, ah1, ah2, ah3, ahibase + off);
            LDMX4(al0, al1, al2, al3, alobase + off);
#pragma unroll
            for (int nt = 0; nt < 2; nt++) {
                MMA_BF16(acc[mt][nt], ah0, ah1, ah2, ah3, bhi[nt][0], bhi[nt][1]);
                MMA_BF16(acc[mt][nt], ah0, ah1, ah2, ah3, blo[nt][0], blo[nt][1]);
                MMA_BF16(acc[mt][nt], al0, al1, al2, al3, bhi[nt][0], bhi[nt][1]);
            }
        }
    }

    // Epilogue
#pragma unroll
    for (int mt = 0; mt < 4; mt++) {
        const int r0 = mt * 16 + g;
#pragma unroll
        for (int nt = 0; nt < 2; nt++) {
            const long col = n0 + 8 * nt + 2 * t;
            *reinterpret_cast<float2*>(Y + (size_t)r0 * NCOLS + col) =
                make_float2(acc[mt][nt][0], acc[mt][nt][1]);
            *reinterpret_cast<float2*>(Y + (size_t)(r0 + 8) * NCOLS + col) =
                make_float2(acc[mt][nt][2], acc[mt][nt][3]);
        }
    }
}

// ---------------------------------------------------------------------------
// Inputs (metadata order): X (64*300000 f32), angles (2016 f32), mus (64 f32).
// ---------------------------------------------------------------------------
extern "C" void kernel_launch(void* const* d_in, const int* in_sizes, int n_in,
                              void* d_out, int out_size) {
    const float* X      = (const float*)d_in[0];
    const float* angles = (const float*)d_in[1];
    const float* mus    = (const float*)d_in[2];
    float* Y            = (float*)d_out;

    build_R_kernel<<<1, NPTS>>>(angles, mus);

    const int blocks = (NCOLS + 127) / 128;   // 2344
    gemm_hmma_kernel<<<blocks, 256>>>(X, Y);
}

// round 6
// speedup vs baseline: 2.9099x; 1.2568x over previous
#include <cuda_runtime.h>
#include <cuda_bf16.h>
#include <cstdint>

#define NPTS   64
#define NANGS  2016
#define NCOLS  300000
#define NSEG   8
#define LSEG   (NANGS / NSEG)   // 252

typedef unsigned int u32;

// Build pipeline buffers (all __device__ — no allocation).
__device__ float g_M[NSEG * NPTS * NPTS];      // segment matrices
__device__ float g_P[(NSEG/2) * NPTS * NPTS];  // level-1 products
__device__ float g_Q[(NSEG/4) * NPTS * NPTS];  // level-2 products
__device__ float g_R[NPTS * NPTS];             // final R

__device__ __forceinline__ u32 smem_u32(const void* p) {
    u32 a;
    asm("{ .reg .u64 t; cvta.to.shared.u64 t, %1; cvt.u32.u64 %0, t; }"
        : "=r"(a) : "l"(p));
    return a;
}

// ---------------------------------------------------------------------------
// Kernel 1: 8 parallel segment matrices. Block s applies rotations
// [s*252, (s+1)*252) of the lexicographic chain to identity.
// Thread j owns column j; rt carried in a register within each t-group.
// ---------------------------------------------------------------------------
__global__ void __launch_bounds__(NPTS, 1)
build_seg_kernel(const float* __restrict__ angles) {
    __shared__ float2 cs[LSEG];
    __shared__ float  Rs[NPTS * NPTS];

    const int j  = threadIdx.x;
    const int i0 = blockIdx.x * LSEG;
    const int i1 = i0 + LSEG;

    for (int i = j; i < LSEG; i += NPTS) {
        float sv, cv;
        __sincosf(angles[i0 + i], &sv, &cv);
        cs[i] = make_float2(cv, sv);
    }
    for (int r = 0; r < NPTS; r++) Rs[r * NPTS + j] = (r == j) ? 1.0f : 0.0f;
    __syncthreads();

#pragma unroll 1
    for (int t = 0; t < NPTS - 1; t++) {
        const int gs = t * (2 * NPTS - 1 - t) / 2;   // start index of group t
        const int glen = NPTS - 1 - t;
        if (gs >= i1) break;
        if (gs + glen <= i0) continue;
        int lo = i0 - gs; if (lo < 0) lo = 0;
        int hi = i1 - gs; if (hi > glen) hi = glen;
        const int bstart = t + 1 + lo;
        const int bend   = t + 1 + hi;

        float rt = Rs[t * NPTS + j];
#pragma unroll 7
        for (int b = bstart; b < bend; b++) {
            const float2 p  = cs[gs + (b - t - 1) - i0];
            const float  rb = Rs[b * NPTS + j];
            Rs[b * NPTS + j] = fmaf(p.y, rt, p.x * rb);
            rt = fmaf(p.x, rt, -(p.y * rb));
        }
        Rs[t * NPTS + j] = rt;
    }

    float* M = g_M + blockIdx.x * (NPTS * NPTS);
    for (int r = 0; r < NPTS; r++) M[r * NPTS + j] = Rs[r * NPTS + j];
}

// ---------------------------------------------------------------------------
// Kernel 2 (x3 levels): pairwise 64x64 products C_p = In_{2p+1} * In_{2p}.
// 2 blocks per product (32-column halves), 256 threads. A staged column-major
// in smem (broadcast loads), B half staged row-major. Final level applies mus.
// ---------------------------------------------------------------------------
__global__ void __launch_bounds__(256, 1)
matprod_kernel(int level, const float* __restrict__ mus) {
    __shared__ float As[NPTS * NPTS];   // column-major: As[k*64 + r]
    __shared__ float Bs[NPTS * 32];     // Bs[k*32 + jl]

    const float* in  = (level == 0) ? g_M : (level == 1) ? g_P : g_Q;
    float*       out = (level == 0) ? g_P : (level == 1) ? g_Q : g_R;
    const int use_mus = (level == 2);

    const int p = blockIdx.x >> 1;
    const int h = blockIdx.x & 1;
    const float* A = in + (2 * p + 1) * (NPTS * NPTS);
    const float* B = in + (2 * p) * (NPTS * NPTS) + h * 32;
    float*       C = out + p * (NPTS * NPTS) + h * 32;

    // Stage A transposed (uncoalesced L2 reads of 16KB — cheap), conflict-free STS.
    for (int idx = threadIdx.x; idx < NPTS * NPTS; idx += 256) {
        const int k = idx >> 6, r = idx & 63;
        As[k * NPTS + r] = A[r * NPTS + k];
    }
    for (int idx = threadIdx.x; idx < NPTS * 32; idx += 256) {
        const int k = idx >> 5, jl = idx & 31;
        Bs[idx] = B[k * NPTS + jl];
    }
    __syncthreads();

    const int jl = threadIdx.x & 31;   // output column within half
    const int rq = threadIdx.x >> 5;   // 8 row-groups of 8 rows

    float acc[8];
#pragma unroll
    for (int i = 0; i < 8; i++) acc[i] = 0.0f;

#pragma unroll 8
    for (int k = 0; k < NPTS; k++) {
        const float  b  = Bs[k * 32 + jl];
        const float4 a0 = *reinterpret_cast<const float4*>(&As[k * NPTS + rq * 8]);
        const float4 a1 = *reinterpret_cast<const float4*>(&As[k * NPTS + rq * 8 + 4]);
        acc[0] = fmaf(a0.x, b, acc[0]);
        acc[1] = fmaf(a0.y, b, acc[1]);
        acc[2] = fmaf(a0.z, b, acc[2]);
        acc[3] = fmaf(a0.w, b, acc[3]);
        acc[4] = fmaf(a1.x, b, acc[4]);
        acc[5] = fmaf(a1.y, b, acc[5]);
        acc[6] = fmaf(a1.z, b, acc[6]);
        acc[7] = fmaf(a1.w, b, acc[7]);
    }

#pragma unroll
    for (int i = 0; i < 8; i++) {
        const int r = rq * 8 + i;
        float v = acc[i];
        if (use_mus) v *= mus[r];
        C[r * NPTS + jl] = v;
    }
}

// ---------------------------------------------------------------------------
// Kernel 3: Y = R @ X via bf16 split-precision HMMA (3-term):
//   Y ~= Rhi@Xhi + Rhi@Xlo + Rlo@Xhi   (fp32 accumulate)
// Warp tile 64x16, ldmatrix.x4 A-frags, 2-deep X prefetch, 3 blocks/SM.
// ---------------------------------------------------------------------------
#define LDR 36

#define CVT_PACK(d, x1, x0) \
    asm("cvt.rn.bf16x2.f32 %0, %1, %2;" : "=r"(d) : "f"(x1), "f"(x0))

#define LDMX4(R0, R1, R2, R3, ADDR)                                            \
    asm volatile("ldmatrix.sync.aligned.m8n8.x4.shared.b16 {%0,%1,%2,%3}, [%4];" \
                 : "=r"(R0), "=r"(R1), "=r"(R2), "=r"(R3) : "r"(ADDR))

#define MMA_BF16(ACC, A0, A1, A2, A3, B0, B1)                                  \
    asm volatile(                                                              \
        "mma.sync.aligned.m16n8k16.row.col.f32.bf16.bf16.f32 "                 \
        "{%0,%1,%2,%3},{%4,%5,%6,%7},{%8,%9},{%0,%1,%2,%3};"                   \
        : "+f"(ACC[0]), "+f"(ACC[1]), "+f"(ACC[2]), "+f"(ACC[3])               \
        : "r"(A0), "r"(A1), "r"(A2), "r"(A3), "r"(B0), "r"(B1))

__global__ void __launch_bounds__(256, 3)
gemm_hmma_kernel(const float* __restrict__ X, float* __restrict__ Y) {
    __shared__ u32 RhiS[NPTS * LDR];
    __shared__ u32 RloS[NPTS * LDR];

    for (int idx = threadIdx.x; idx < NPTS * 32; idx += 256) {
        const int row = idx >> 5, kp = idx & 31;
        const float x0 = g_R[row * NPTS + 2 * kp];
        const float x1 = g_R[row * NPTS + 2 * kp + 1];
        u32 hh; CVT_PACK(hh, x1, x0);
        const float h0 = __uint_as_float(hh << 16);
        const float h1 = __uint_as_float(hh & 0xFFFF0000u);
        u32 ll; CVT_PACK(ll, x1 - h1, x0 - h0);
        RhiS[row * LDR + kp] = hh;
        RloS[row * LDR + kp] = ll;
    }
    __syncthreads();

    const int warp = threadIdx.x >> 5;
    const int lane = threadIdx.x & 31;
    const int g = lane >> 2;
    const int t = lane & 3;

    const long n0 = (long)blockIdx.x * 128 + warp * 16;
    if (n0 + 16 > NCOLS) return;

    const int r8   = lane & 7;
    const int selm = (lane >> 3) & 1;
    const int selk = (lane >> 4) & 1;
    const u32 laneoff = (u32)(((selm * 8 + r8) * LDR + selk * 4) * 4);
    const u32 ahibase = smem_u32(RhiS) + laneoff;
    const u32 alobase = smem_u32(RloS) + laneoff;

    float acc[4][2][4];
#pragma unroll
    for (int mt = 0; mt < 4; mt++)
#pragma unroll
        for (int nt = 0; nt < 2; nt++)
#pragma unroll
            for (int q = 0; q < 4; q++) acc[mt][nt][q] = 0.0f;

    const float* __restrict__ xb = X + n0 + g;
    float raw[2][8];

#define LOADK(BUF, KS)                                                         \
    do {                                                                       \
        const size_t o  = (size_t)((KS)*16 + 2 * t) * NCOLS;                   \
        const size_t o8 = o + (size_t)8 * NCOLS;                               \
        raw[BUF][0] = xb[o];      raw[BUF][1] = xb[o + NCOLS];                 \
        raw[BUF][2] = xb[o8];     raw[BUF][3] = xb[o8 + NCOLS];                \
        raw[BUF][4] = xb[o + 8];  raw[BUF][5] = xb[o + NCOLS + 8];             \
        raw[BUF][6] = xb[o8 + 8]; raw[BUF][7] = xb[o8 + NCOLS + 8];            \
    } while (0)

    LOADK(0, 0);
    LOADK(1, 1);

#pragma unroll
    for (int ks = 0; ks < 4; ks++) {
        const int cur = ks & 1;

        u32 bhi[2][2], blo[2][2];
#pragma unroll
        for (int nt = 0; nt < 2; nt++) {
#pragma unroll
            for (int h2 = 0; h2 < 2; h2++) {
                const float x0 = raw[cur][nt * 4 + h2 * 2];
                const float x1 = raw[cur][nt * 4 + h2 * 2 + 1];
                u32 hh; CVT_PACK(hh, x1, x0);
                const float h0 = __uint_as_float(hh << 16);
                const float h1 = __uint_as_float(hh & 0xFFFF0000u);
                u32 ll; CVT_PACK(ll, x1 - h1, x0 - h0);
                bhi[nt][h2] = hh;
                blo[nt][h2] = ll;
            }
        }

        if (ks + 2 < 4) LOADK(cur, ks + 2);   // prefetch into freed buffer

#pragma unroll
        for (int mt = 0; mt < 4; mt++) {
            const u32 off = (u32)(mt * 16 * LDR * 4 + ks * 32);
            u32 ah0, ah1, ah2, ah3, al0, al1, al2, al3;
            LDMX4(ah0, ah1, ah2, ah3, ahibase + off);
            LDMX4(al0, al1, al2, al3, alobase + off);
#pragma unroll
            for (int nt = 0; nt < 2; nt++) {
                MMA_BF16(acc[mt][nt], ah0, ah1, ah2, ah3, bhi[nt][0], bhi[nt][1]);
                MMA_BF16(acc[mt][nt], ah0, ah1, ah2, ah3, blo[nt][0], blo[nt][1]);
                MMA_BF16(acc[mt][nt], al0, al1, al2, al3, bhi[nt][0], bhi[nt][1]);
            }
        }
    }
#undef LOADK

#pragma unroll
    for (int mt = 0; mt < 4; mt++) {
        const int r0 = mt * 16 + g;
#pragma unroll
        for (int nt = 0; nt < 2; nt++) {
            const long col = n0 + 8 * nt + 2 * t;
            *reinterpret_cast<float2*>(Y + (size_t)r0 * NCOLS + col) =
                make_float2(acc[mt][nt][0], acc[mt][nt][1]);
            *reinterpret_cast<float2*>(Y + (size_t)(r0 + 8) * NCOLS + col) =
                make_float2(acc[mt][nt][2], acc[mt][nt][3]);
        }
    }
}

// ---------------------------------------------------------------------------
// Inputs (metadata order): X (64*300000 f32), angles (2016 f32), mus (64 f32).
// ---------------------------------------------------------------------------
extern "C" void kernel_launch(void* const* d_in, const int* in_sizes, int n_in,
                              void* d_out, int out_size) {
    const float* X      = (const float*)d_in[0];
    const float* angles = (const float*)d_in[1];
    const float* mus    = (const float*)d_in[2];
    float* Y            = (float*)d_out;

    build_seg_kernel<<<NSEG, NPTS>>>(angles);
    matprod_kernel<<<NSEG, 256>>>(0, mus);        // 8 blocks: 4 products
    matprod_kernel<<<NSEG / 2, 256>>>(1, mus);    // 4 blocks: 2 products
    matprod_kernel<<<NSEG / 4, 256>>>(2, mus);    // 2 blocks: 1 product (+mus)

    const int blocks = (NCOLS + 127) / 128;       // 2344
    gemm_hmma_kernel<<<blocks, 256>>>(X, Y);
}